// round 11
// baseline (speedup 1.0000x reference)
#include <cuda_runtime.h>

#define B_TOT   16
#define CIN     64
#define COUT    64
#define S_LEN   1024
#define KW      3
#define STILE   32
#define POSN    (STILE + 2)     // 34 input positions per tile (halo of 1 each side)
#define BH      8               // batches per block
#define OTILE   4               // outputs per thread
#define OGN     8               // o-groups per c-half
#define OBLK    (OGN * OTILE)   // 32 outputs per block
#define CHALF   (CIN / 2)       // 32 c per warp-half
#define NTHREADS 512            // 16 warps: [c-half][o-group]
#define SK      (S_LEN * KW)            // per-c weight stride (floats)
#define OCS     (CIN * S_LEN * KW)      // per-o weight stride (floats)
#define SMEM_FLOATS (CIN * BH * POSN)   // 64*8*34 = 17408 floats = 69632 B

// Load one c-iteration's 4x3 weights into a register buffer.
#define WLOAD(BUF, PTR)                                          \
    _Pragma("unroll")                                            \
    for (int j = 0; j < OTILE; j++) {                            \
        _Pragma("unroll")                                        \
        for (int k = 0; k < KW; k++)                             \
            BUF[j][k] = (PTR)[(size_t)j * OCS + k];              \
    }

// One c-iteration of FMAs: b-outer, only 3 x values live.
#define CSTEP(BUF, XC)                                           \
    _Pragma("unroll")                                            \
    for (int b = 0; b < BH; b++) {                               \
        const float x0 = (XC)[b * POSN + 0];                     \
        const float x1 = (XC)[b * POSN + 1];                     \
        const float x2 = (XC)[b * POSN + 2];                     \
        _Pragma("unroll")                                        \
        for (int j = 0; j < OTILE; j++) {                        \
            acc[j][b] += BUF[j][0] * x0;                         \
            acc[j][b] += BUF[j][1] * x1;                         \
            acc[j][b] += BUF[j][2] * x2;                         \
        }                                                        \
    }

__global__ void __launch_bounds__(NTHREADS)
locon1d_kernel(const float* __restrict__ X,     // (B, Cin, S)
               const float* __restrict__ W,     // (Cout, Cin, S, K)
               const float* __restrict__ Bias,  // (Cout, S)
               float* __restrict__ Out)         // (B, Cout, S)
{
    extern __shared__ float shx[];   // [c][b][pos] -> (c*BH + b)*POSN + pos

    const int s0     = blockIdx.x * STILE;
    const int o0base = blockIdx.y * OBLK;
    const int b0     = blockIdx.z * BH;
    const int tid    = threadIdx.x;
    const int sl     = tid & 31;          // lane = consecutive s
    const int wid    = tid >> 5;          // 0..15
    const int og     = wid & 7;           // o-group
    const int ch     = wid >> 3;          // c-half: 0 or 1

    // ── Input tile fill: warp -> (batch, c-half). No div/mod; coalesced rows.
    {
        const int  bf    = wid >> 1;                 // batch this warp fills
        const int  cbase = (wid & 1) * CHALF;        // 32 c-rows per warp
        const float* xb  = X + ((size_t)(b0 + bf) * CIN + cbase) * S_LEN;
        float*       shb = shx + ((size_t)cbase * BH + bf) * POSN;
        const int  sg    = s0 - 1 + sl;
        const bool m1    = (unsigned)sg < (unsigned)S_LEN;
        const int  sg2   = s0 + 31 + sl;
        const bool m2    = (sl < 2) && ((unsigned)sg2 < (unsigned)S_LEN);
        #pragma unroll 4
        for (int c = 0; c < CHALF; c++) {
            shb[(size_t)c * (BH * POSN) + sl] =
                m1 ? xb[(size_t)c * S_LEN + sg] : 0.0f;
            if (sl < 2)
                shb[(size_t)c * (BH * POSN) + 32 + sl] =
                    m2 ? xb[(size_t)c * S_LEN + sg2] : 0.0f;
        }
    }
    __syncthreads();

    const int s  = s0 + sl;
    const int o0 = o0base + og * OTILE;

    // acc[j][b]: 4 outputs x 8 batches = 32 registers.
    float acc[OTILE][BH];
    #pragma unroll
    for (int j = 0; j < OTILE; j++) {
        float bv = (ch == 0) ? Bias[(size_t)(o0 + j) * S_LEN + s] : 0.0f;
        #pragma unroll
        for (int b = 0; b < BH; b++) acc[j][b] = bv;
    }

    // ── Main loop: explicit double-buffered weight prefetch (wA/wB ping-pong).
    const float* wc = W + (size_t)o0 * OCS
                        + (size_t)(ch * CHALF) * SK
                        + (size_t)s * KW;
    const float* xc = shx + (size_t)(ch * CHALF) * (BH * POSN) + sl;

    float wA[OTILE][KW], wB[OTILE][KW];
    WLOAD(wA, wc);                 // preload ci = 0
    wc += SK;

    #pragma unroll 1
    for (int ci = 0; ci < CHALF; ci += 2) {
        WLOAD(wB, wc);             // prefetch ci+1 while computing ci
        wc += SK;
        CSTEP(wA, xc);
        xc += BH * POSN;
        if (ci + 2 < CHALF) {      // prefetch ci+2 while computing ci+1
            WLOAD(wA, wc);
        }
        wc += SK;
        CSTEP(wB, xc);
        xc += BH * POSN;
    }

    // ── Cross-half reduction through smem (x tile is dead; reuse shx).
    __syncthreads();
    const int t2 = og * 32 + sl;            // 0..255 within a c-half
    if (ch == 1) {
        #pragma unroll
        for (int j = 0; j < OTILE; j++)
            #pragma unroll
            for (int b = 0; b < BH; b++)
                shx[(j * BH + b) * 256 + t2] = acc[j][b];
    }
    __syncthreads();
    if (ch == 0) {
        #pragma unroll
        for (int j = 0; j < OTILE; j++) {
            #pragma unroll
            for (int b = 0; b < BH; b++) {
                float v = acc[j][b] + shx[(j * BH + b) * 256 + t2];
                Out[((size_t)(b0 + b) * COUT + (o0 + j)) * S_LEN + s] = v;
            }
        }
    }
}

extern "C" void kernel_launch(void* const* d_in, const int* in_sizes, int n_in,
                              void* d_out, int out_size) {
    const float* x    = (const float*)d_in[0];
    const float* w    = (const float*)d_in[1];
    const float* bias = (const float*)d_in[2];
    float* out        = (float*)d_out;

    const int smem_bytes = SMEM_FLOATS * (int)sizeof(float);  // 69632 B > 48K -> opt-in
    cudaFuncSetAttribute(locon1d_kernel,
                         cudaFuncAttributeMaxDynamicSharedMemorySize, smem_bytes);

    dim3 grid(S_LEN / STILE, COUT / OBLK, B_TOT / BH);  // (32, 2, 2) = 128 blocks
    locon1d_kernel<<<grid, NTHREADS, smem_bytes>>>(x, w, bias, out);
}